// round 14
// baseline (speedup 1.0000x reference)
#include <cuda_runtime.h>
#include <cuda_fp16.h>
#include <mma.h>
#include <math.h>
#include <stdint.h>

using namespace nvcuda;

#define N_MAX 100000
#define E_MAX 1600000

// ---------------- device scratch (static, no allocation) ----------------
__device__ int    g_deg[N_MAX];
__device__ int    g_pos[E_MAX];      // within-segment position per edge
__device__ int    g_rowstart[N_MAX];
__device__ int    g_total;
__device__ int    g_ebuf[E_MAX];
__device__ __align__(16) __half g_y1h[N_MAX * 64]; // fp16(x @ W_l1)
__device__ __align__(16) __half g_r1h[N_MAX * 64]; // fp16(x @ W_r1 + b_l1)
__device__ __align__(16) __half g_hid[N_MAX * 64]; // fp16(relu(mean + root))
__device__ __align__(16) __half g_y2h[N_MAX * 40]; // fp16(hid @ W_l2)
__device__ __align__(16) __half g_r2h[N_MAX * 40]; // fp16(hid @ W_r2 + b_l2)

// ---------------- CSR build (order-free segments, position-cached) ------
__global__ void count_deg_kernel(const int* __restrict__ dst, int e) {
    int i = blockIdx.x * blockDim.x + threadIdx.x;
    if (i == 0) g_total = 0;  // consumed only by assign_kernel (stream-ordered after)
    if (i < e) g_pos[i] = atomicAdd(&g_deg[dst[i]], 1);
}

__global__ void assign_kernel(int n) {
    __shared__ int wsum[32];
    __shared__ int blockbase;
    int t = threadIdx.x;
    int i = blockIdx.x * blockDim.x + t;
    int v = (i < n) ? g_deg[i] : 0;
    int x = v;
#pragma unroll
    for (int o = 1; o < 32; o <<= 1) {
        int u = __shfl_up_sync(0xffffffffu, x, o);
        if ((t & 31) >= o) x += u;
    }
    if ((t & 31) == 31) wsum[t >> 5] = x;
    __syncthreads();
    if (t < 32) {
        int w = (t < 8) ? wsum[t] : 0;
#pragma unroll
        for (int o = 1; o < 8; o <<= 1) {
            int u = __shfl_up_sync(0xffffffffu, w, o);
            if (t >= o) w += u;
        }
        if (t == 7) blockbase = atomicAdd(&g_total, w);
        wsum[t] = w;
    }
    __syncthreads();
    int base = blockbase + ((t >= 32) ? wsum[(t >> 5) - 1] : 0);
    if (i < n) g_rowstart[i] = base + x - v;
}

__global__ void fill_csr_kernel(const int* __restrict__ src,
                                const int* __restrict__ dst, int e) {
    int i = blockIdx.x * blockDim.x + threadIdx.x;
    if (i < e) g_ebuf[g_rowstart[dst[i]] + g_pos[i]] = src[i];  // no atomic
}

// ------- layer-1 HMMA, single pass: C[128,128] = x_tile @ [Wl1|Wr1] -----
#define LDA1 136
#define LDC1 132
__global__ __launch_bounds__(512) void gemm1_kernel(
    const float* __restrict__ x, const float* __restrict__ Wl,
    const float* __restrict__ Wr, const float* __restrict__ bl, int n) {
    extern __shared__ char smem[];
    __half* As = (__half*)smem;                        // [128][136] = 34816 B
    __half* Bs = (__half*)(smem + 128 * LDA1 * 2);     // [128][136] = 34816 B
    float*  Cs = (float*)smem;                         // [128][132] alias
    int tid = threadIdx.x;
    int node0 = blockIdx.x * 128;

    for (int i = tid; i < 128 * 32; i += 512) {
        int row = i >> 5, c4 = i & 31;
        int gr = node0 + row;
        float4 v = (gr < n) ? ((const float4*)x)[gr * 32 + c4]
                            : make_float4(0.f, 0.f, 0.f, 0.f);
        *(__half2*)&As[row * LDA1 + c4 * 4] = __floats2half2_rn(v.x, v.y);
        *(__half2*)&As[row * LDA1 + c4 * 4 + 2] = __floats2half2_rn(v.z, v.w);
    }
    for (int i = tid; i < 4096; i += 512) {
        int hs = i >> 11;
        int f = i & 2047;
        int k = f >> 4, c4 = f & 15;
        float4 v = hs ? ((const float4*)Wr)[f] : ((const float4*)Wl)[f];
        int col = hs * 64 + c4 * 4;
        *(__half2*)&Bs[k * LDA1 + col] = __floats2half2_rn(v.x, v.y);
        *(__half2*)&Bs[k * LDA1 + col + 2] = __floats2half2_rn(v.z, v.w);
    }
    __syncthreads();

    int wid = tid >> 5;
    int wr = (wid & 7) * 16;
    int wc = (wid >> 3) * 64;
    wmma::fragment<wmma::accumulator, 16, 16, 16, float> acc[4];
#pragma unroll
    for (int j = 0; j < 4; j++) wmma::fill_fragment(acc[j], 0.f);

#pragma unroll
    for (int k = 0; k < 128; k += 16) {
        wmma::fragment<wmma::matrix_a, 16, 16, 16, __half, wmma::row_major> af;
        wmma::load_matrix_sync(af, &As[wr * LDA1 + k], LDA1);
#pragma unroll
        for (int j = 0; j < 4; j++) {
            wmma::fragment<wmma::matrix_b, 16, 16, 16, __half, wmma::row_major> bf;
            wmma::load_matrix_sync(bf, &Bs[k * LDA1 + wc + j * 16], LDA1);
            wmma::mma_sync(acc[j], af, bf, acc[j]);
        }
    }
    __syncthreads();
#pragma unroll
    for (int j = 0; j < 4; j++)
        wmma::store_matrix_sync(&Cs[wr * LDC1 + wc + j * 16], acc[j], LDC1,
                                wmma::mem_row_major);
    __syncthreads();

    for (int c = tid; c < 1024; c += 512) {         // y1h: 8 uint4/row
        int row = c >> 3, ci = c & 7;
        int m = node0 + row;
        if (m < n) {
            const float* cp = &Cs[row * LDC1 + ci * 8];
            __half2 h0 = __floats2half2_rn(cp[0], cp[1]);
            __half2 h1 = __floats2half2_rn(cp[2], cp[3]);
            __half2 h2 = __floats2half2_rn(cp[4], cp[5]);
            __half2 h3 = __floats2half2_rn(cp[6], cp[7]);
            uint4 u;
            u.x = *reinterpret_cast<uint32_t*>(&h0);
            u.y = *reinterpret_cast<uint32_t*>(&h1);
            u.z = *reinterpret_cast<uint32_t*>(&h2);
            u.w = *reinterpret_cast<uint32_t*>(&h3);
            ((uint4*)(g_y1h + (size_t)m * 64))[ci] = u;
        }
    }
    for (int c = tid; c < 1024; c += 512) {         // r1h: 8 uint4/row, +bias
        int row = c >> 3, ci = c & 7;
        int m = node0 + row;
        if (m < n) {
            const float* cp = &Cs[row * LDC1 + 64 + ci * 8];
            const float* bp = &bl[ci * 8];
            __half2 h0 = __floats2half2_rn(cp[0] + bp[0], cp[1] + bp[1]);
            __half2 h1 = __floats2half2_rn(cp[2] + bp[2], cp[3] + bp[3]);
            __half2 h2 = __floats2half2_rn(cp[4] + bp[4], cp[5] + bp[5]);
            __half2 h3 = __floats2half2_rn(cp[6] + bp[6], cp[7] + bp[7]);
            uint4 u;
            u.x = *reinterpret_cast<uint32_t*>(&h0);
            u.y = *reinterpret_cast<uint32_t*>(&h1);
            u.z = *reinterpret_cast<uint32_t*>(&h2);
            u.w = *reinterpret_cast<uint32_t*>(&h3);
            ((uint4*)(g_r1h + (size_t)m * 64))[ci] = u;
        }
    }
}

// ------- combine layer 1 over node range [start, end) --------------------
__global__ void combine1_kernel(int start, int end) {
    int node = start + ((blockIdx.x * blockDim.x + threadIdx.x) >> 5);
    int lane = threadIdx.x & 31;
    if (node >= end) return;
    int s = g_rowstart[node];
    int dg = g_deg[node];
    int e = s + dg;
    float inv = 1.f / (float)max(dg, 1);
    const __half2* y1 = (const __half2*)g_y1h;
    float a0 = 0.f, a1 = 0.f, b0 = 0.f, b1 = 0.f;
    float c0 = 0.f, c1 = 0.f, d0 = 0.f, d1 = 0.f;
    for (int base = s; base < e; base += 32) {
        int cnt = min(32, e - base);
        int idx = (lane < cnt) ? g_ebuf[base + lane] : 0;
        int j = 0;
        for (; j + 4 <= cnt; j += 4) {
            int n0 = __shfl_sync(0xffffffffu, idx, j);
            int n1 = __shfl_sync(0xffffffffu, idx, j + 1);
            int n2 = __shfl_sync(0xffffffffu, idx, j + 2);
            int n3 = __shfl_sync(0xffffffffu, idx, j + 3);
            float2 v0 = __half22float2(y1[n0 * 32 + lane]);
            float2 v1 = __half22float2(y1[n1 * 32 + lane]);
            float2 v2 = __half22float2(y1[n2 * 32 + lane]);
            float2 v3 = __half22float2(y1[n3 * 32 + lane]);
            a0 += v0.x; a1 += v0.y;
            b0 += v1.x; b1 += v1.y;
            c0 += v2.x; c1 += v2.y;
            d0 += v3.x; d1 += v3.y;
        }
        for (; j < cnt; j++) {
            int n0 = __shfl_sync(0xffffffffu, idx, j);
            float2 v0 = __half22float2(y1[n0 * 32 + lane]);
            a0 += v0.x; a1 += v0.y;
        }
    }
    a0 += b0 + c0 + d0;
    a1 += b1 + c1 + d1;
    float2 r = __half22float2(*(const __half2*)&g_r1h[node * 64 + lane * 2]);
    float h0 = fmaxf(a0 * inv + r.x, 0.f);
    float h1 = fmaxf(a1 * inv + r.y, 0.f);
    *(__half2*)&g_hid[node * 64 + lane * 2] = __floats2half2_rn(h0, h1);
}

// ------- layer-2 HMMA over tile range starting at node base --------------
#define LDA2 72
#define LDB2 88
__global__ __launch_bounds__(256) void gemm2_kernel(
    const float* __restrict__ Wl, const float* __restrict__ Wr,
    const float* __restrict__ bl, int base, int n) {
    extern __shared__ char smem[];
    __half* As = (__half*)smem;                       // [128][72]
    __half* Bs = (__half*)(smem + 128 * LDA2 * 2);    // [64][88]
    float*  Cs = (float*)smem;                        // [128][88] alias
    int tid = threadIdx.x;
    int node0 = base + blockIdx.x * 128;

    for (int i = tid; i < 128 * 8; i += 256) {
        int row = i >> 3, c8 = i & 7;
        int gr = node0 + row;
        uint4 v = (gr < n) ? ((const uint4*)g_hid)[gr * 8 + c8] : make_uint4(0, 0, 0, 0);
        *(uint4*)&As[row * LDA2 + c8 * 8] = v;
    }
    for (int i = tid; i < 1280; i += 256) {
        int hs = i >= 640;
        int f = hs ? i - 640 : i;
        int k = f / 10, c4 = f % 10;
        float4 v = hs ? ((const float4*)Wr)[f] : ((const float4*)Wl)[f];
        int col = hs * 40 + c4 * 4;
        *(__half2*)&Bs[k * LDB2 + col] = __floats2half2_rn(v.x, v.y);
        *(__half2*)&Bs[k * LDB2 + col + 2] = __floats2half2_rn(v.z, v.w);
    }
    for (int i = tid; i < 64 * 8; i += 256) {
        int k = i >> 3, c = i & 7;
        Bs[k * LDB2 + 80 + c] = __half(0.f);
    }
    __syncthreads();

    int wid = tid >> 5;
    int wr = wid * 16;
    wmma::fragment<wmma::accumulator, 16, 16, 16, float> acc[5];
#pragma unroll
    for (int j = 0; j < 5; j++) wmma::fill_fragment(acc[j], 0.f);
#pragma unroll
    for (int k = 0; k < 64; k += 16) {
        wmma::fragment<wmma::matrix_a, 16, 16, 16, __half, wmma::row_major> af;
        wmma::load_matrix_sync(af, &As[wr * LDA2 + k], LDA2);
#pragma unroll
        for (int j = 0; j < 5; j++) {
            wmma::fragment<wmma::matrix_b, 16, 16, 16, __half, wmma::row_major> bf;
            wmma::load_matrix_sync(bf, &Bs[k * LDB2 + j * 16], LDB2);
            wmma::mma_sync(acc[j], af, bf, acc[j]);
        }
    }
    __syncthreads();
#pragma unroll
    for (int j = 0; j < 5; j++)
        wmma::store_matrix_sync(&Cs[wr * LDB2 + j * 16], acc[j], LDB2,
                                wmma::mem_row_major);
    __syncthreads();

    for (int c = tid; c < 640; c += 256) {
        int row = c / 5, ci = c % 5;
        int m = node0 + row;
        if (m < n) {
            const float* cp = &Cs[row * LDB2 + ci * 8];
            __half2 h0 = __floats2half2_rn(cp[0], cp[1]);
            __half2 h1 = __floats2half2_rn(cp[2], cp[3]);
            __half2 h2 = __floats2half2_rn(cp[4], cp[5]);
            __half2 h3 = __floats2half2_rn(cp[6], cp[7]);
            uint4 u;
            u.x = *reinterpret_cast<uint32_t*>(&h0);
            u.y = *reinterpret_cast<uint32_t*>(&h1);
            u.z = *reinterpret_cast<uint32_t*>(&h2);
            u.w = *reinterpret_cast<uint32_t*>(&h3);
            ((uint4*)(g_y2h + (size_t)m * 40))[ci] = u;
        }
    }
    for (int c = tid; c < 640; c += 256) {
        int row = c / 5, ci = c % 5;
        int m = node0 + row;
        if (m < n) {
            const float* cp = &Cs[row * LDB2 + 40 + ci * 8];
            const float* bp = &bl[ci * 8];
            __half2 h0 = __floats2half2_rn(cp[0] + bp[0], cp[1] + bp[1]);
            __half2 h1 = __floats2half2_rn(cp[2] + bp[2], cp[3] + bp[3]);
            __half2 h2 = __floats2half2_rn(cp[4] + bp[4], cp[5] + bp[5]);
            __half2 h3 = __floats2half2_rn(cp[6] + bp[6], cp[7] + bp[7]);
            uint4 u;
            u.x = *reinterpret_cast<uint32_t*>(&h0);
            u.y = *reinterpret_cast<uint32_t*>(&h1);
            u.z = *reinterpret_cast<uint32_t*>(&h2);
            u.w = *reinterpret_cast<uint32_t*>(&h3);
            ((uint4*)(g_r2h + (size_t)m * 40))[ci] = u;
        }
    }
}

// ------- combine layer 2: out = log_softmax(gather_mean(y2) + r2) -------
__global__ void combine2_kernel(float* __restrict__ out, int n) {
    int node = (blockIdx.x * blockDim.x + threadIdx.x) >> 5;
    int lane = threadIdx.x & 31;
    if (node >= n) return;
    int s = g_rowstart[node];
    int dg = g_deg[node];
    int e = s + dg;
    float inv = 1.f / (float)max(dg, 1);
    const __half2* y2 = (const __half2*)g_y2h;
    bool act = lane < 20;
    float a0 = 0.f, a1 = 0.f, b0 = 0.f, b1 = 0.f;
    float c0 = 0.f, c1 = 0.f, d0 = 0.f, d1 = 0.f;
    for (int base = s; base < e; base += 32) {
        int cnt = min(32, e - base);
        int idx = (lane < cnt) ? g_ebuf[base + lane] : 0;
        int j = 0;
        for (; j + 4 <= cnt; j += 4) {
            int n0 = __shfl_sync(0xffffffffu, idx, j);
            int n1 = __shfl_sync(0xffffffffu, idx, j + 1);
            int n2 = __shfl_sync(0xffffffffu, idx, j + 2);
            int n3 = __shfl_sync(0xffffffffu, idx, j + 3);
            if (act) {
                float2 v0 = __half22float2(y2[n0 * 20 + lane]);
                float2 v1 = __half22float2(y2[n1 * 20 + lane]);
                float2 v2 = __half22float2(y2[n2 * 20 + lane]);
                float2 v3 = __half22float2(y2[n3 * 20 + lane]);
                a0 += v0.x; a1 += v0.y;
                b0 += v1.x; b1 += v1.y;
                c0 += v2.x; c1 += v2.y;
                d0 += v3.x; d1 += v3.y;
            }
        }
        for (; j < cnt; j++) {
            int n0 = __shfl_sync(0xffffffffu, idx, j);
            if (act) {
                float2 v0 = __half22float2(y2[n0 * 20 + lane]);
                a0 += v0.x; a1 += v0.y;
            }
        }
    }
    a0 += b0 + c0 + d0;
    a1 += b1 + c1 + d1;
    const float NEG_INF = __int_as_float(0xff800000);
    float v0 = NEG_INF, v1 = NEG_INF;
    if (act) {
        float2 r = __half22float2(*(const __half2*)&g_r2h[node * 40 + 2 * lane]);
        v0 = a0 * inv + r.x;
        v1 = a1 * inv + r.y;
    }
    float m = fmaxf(v0, v1);
#pragma unroll
    for (int o = 16; o > 0; o >>= 1) m = fmaxf(m, __shfl_xor_sync(0xffffffffu, m, o));
    float sum = act ? (expf(v0 - m) + expf(v1 - m)) : 0.f;
#pragma unroll
    for (int o = 16; o > 0; o >>= 1) sum += __shfl_xor_sync(0xffffffffu, sum, o);
    float lse = logf(sum);
    if (act) {
        out[node * 40 + 2 * lane] = v0 - m - lse;
        out[node * 40 + 2 * lane + 1] = v1 - m - lse;
    }
}

// ---------------- launch ----------------
extern "C" void kernel_launch(void* const* d_in, const int* in_sizes, int n_in,
                              void* d_out, int out_size) {
    const float* x   = (const float*)d_in[0];
    const int*   ei  = (const int*)d_in[1];   // int64 inputs delivered as int32
    const float* Wl1 = (const float*)d_in[2];
    const float* bl1 = (const float*)d_in[3];
    const float* Wr1 = (const float*)d_in[4];
    const float* Wl2 = (const float*)d_in[5];
    const float* bl2 = (const float*)d_in[6];
    const float* Wr2 = (const float*)d_in[7];
    float* out = (float*)d_out;

    int n = in_sizes[0] / 128;
    int e = in_sizes[1] / 2;
    const int* src = ei;
    const int* dst = ei + e;

    const int SMEM1 = 128 * LDA1 * 2 * 2;   // 69632 B
    const int SMEM2 = 128 * LDB2 * 4;       // 45056 B
    cudaFuncSetAttribute(gemm1_kernel, cudaFuncAttributeMaxDynamicSharedMemorySize, SMEM1);
    cudaFuncSetAttribute(gemm2_kernel, cudaFuncAttributeMaxDynamicSharedMemorySize, SMEM2);

    void* deg_ptr = nullptr;
    cudaGetSymbolAddress(&deg_ptr, g_deg);

    cudaStream_t s2;
    cudaStreamCreateWithFlags(&s2, cudaStreamNonBlocking);
    cudaEvent_t evFork, evJoin, evC1h0, evG2h0;
    cudaEventCreateWithFlags(&evFork, cudaEventDisableTiming);
    cudaEventCreateWithFlags(&evJoin, cudaEventDisableTiming);
    cudaEventCreateWithFlags(&evC1h0, cudaEventDisableTiming);
    cudaEventCreateWithFlags(&evG2h0, cudaEventDisableTiming);

    cudaEventRecord(evFork, 0);
    cudaStreamWaitEvent(s2, evFork, 0);

    // CSR chain (side stream): memset, count(+pos), assign, fill(no atomic)
    cudaMemsetAsync(deg_ptr, 0, (size_t)n * sizeof(int), s2);
    count_deg_kernel<<<(e + 255) / 256, 256, 0, s2>>>(dst, e);
    assign_kernel<<<(n + 255) / 256, 256, 0, s2>>>(n);
    fill_csr_kernel<<<(e + 255) / 256, 256, 0, s2>>>(src, dst, e);
    cudaEventRecord(evJoin, s2);

    int nblk = (n + 127) / 128;
    gemm1_kernel<<<nblk, 512, SMEM1>>>(x, Wl1, Wr1, bl1, n);

    // pipelined tail: combine1(h0) -> {gemm2(h0) || combine1(h1)} -> gemm2(h1)
    int tiles0 = nblk / 2;
    int n0 = tiles0 * 128;               // h0 node count (tile-aligned)
    int tiles1 = nblk - tiles0;

    cudaStreamWaitEvent(0, evJoin, 0);
    combine1_kernel<<<(n0 * 32 + 255) / 256, 256>>>(0, n0);
    cudaEventRecord(evC1h0, 0);

    cudaStreamWaitEvent(s2, evC1h0, 0);
    gemm2_kernel<<<tiles0, 256, SMEM2, s2>>>(Wl2, Wr2, bl2, 0, n);
    cudaEventRecord(evG2h0, s2);

    combine1_kernel<<<((n - n0) * 32 + 255) / 256, 256>>>(n0, n);
    gemm2_kernel<<<tiles1, 256, SMEM2>>>(Wl2, Wr2, bl2, n0, n);

    cudaStreamWaitEvent(0, evG2h0, 0);
    combine2_kernel<<<(n * 32 + 255) / 256, 256>>>(out, n);
}

// round 15
// speedup vs baseline: 1.0420x; 1.0420x over previous
#include <cuda_runtime.h>
#include <cuda_fp16.h>
#include <mma.h>
#include <math.h>
#include <stdint.h>

using namespace nvcuda;

#define N_MAX 100000
#define E_MAX 1600000

// ---------------- device scratch (static, no allocation) ----------------
__device__ int    g_deg[N_MAX];
__device__ int    g_pos[E_MAX];      // within-segment position per edge
__device__ int    g_rowstart[N_MAX];
__device__ int    g_total;
__device__ int    g_ebuf[E_MAX];
__device__ __align__(16) __half g_y1h[N_MAX * 64]; // fp16(x @ W_l1)
__device__ __align__(16) __half g_r1h[N_MAX * 64]; // fp16(x @ W_r1 + b_l1)
__device__ __align__(16) __half g_hid[N_MAX * 64]; // fp16(relu(mean + root))
__device__ __align__(16) __half g_y2h[N_MAX * 40]; // fp16(hid @ W_l2)
__device__ __align__(16) __half g_r2h[N_MAX * 40]; // fp16(hid @ W_r2 + b_l2)

// ---------------- CSR build (order-free segments, position-cached) ------
__global__ void count_deg_kernel(const int* __restrict__ dst, int e) {
    int i = blockIdx.x * blockDim.x + threadIdx.x;
    if (i == 0) g_total = 0;  // consumed only by assign_kernel (stream-ordered after)
    if (i < e) g_pos[i] = atomicAdd(&g_deg[dst[i]], 1);
}

__global__ void assign_kernel(int n) {
    __shared__ int wsum[32];
    __shared__ int blockbase;
    int t = threadIdx.x;
    int i = blockIdx.x * blockDim.x + t;
    int v = (i < n) ? g_deg[i] : 0;
    int x = v;
#pragma unroll
    for (int o = 1; o < 32; o <<= 1) {
        int u = __shfl_up_sync(0xffffffffu, x, o);
        if ((t & 31) >= o) x += u;
    }
    if ((t & 31) == 31) wsum[t >> 5] = x;
    __syncthreads();
    if (t < 32) {
        int w = (t < 8) ? wsum[t] : 0;
#pragma unroll
        for (int o = 1; o < 8; o <<= 1) {
            int u = __shfl_up_sync(0xffffffffu, w, o);
            if (t >= o) w += u;
        }
        if (t == 7) blockbase = atomicAdd(&g_total, w);
        wsum[t] = w;
    }
    __syncthreads();
    int base = blockbase + ((t >= 32) ? wsum[(t >> 5) - 1] : 0);
    if (i < n) g_rowstart[i] = base + x - v;
}

__global__ void fill_csr_kernel(const int* __restrict__ src,
                                const int* __restrict__ dst, int e) {
    int i = blockIdx.x * blockDim.x + threadIdx.x;
    if (i < e) g_ebuf[g_rowstart[dst[i]] + g_pos[i]] = src[i];  // no atomic
}

// ------- layer-1 HMMA, single pass: C[128,128] = x_tile @ [Wl1|Wr1] -----
#define LDA1 136
#define LDC1 132
__global__ __launch_bounds__(512) void gemm1_kernel(
    const float* __restrict__ x, const float* __restrict__ Wl,
    const float* __restrict__ Wr, const float* __restrict__ bl, int n) {
    extern __shared__ char smem[];
    __half* As = (__half*)smem;                        // [128][136] = 34816 B
    __half* Bs = (__half*)(smem + 128 * LDA1 * 2);     // [128][136] = 34816 B
    float*  Cs = (float*)smem;                         // [128][132] alias
    int tid = threadIdx.x;
    int node0 = blockIdx.x * 128;

    for (int i = tid; i < 128 * 32; i += 512) {
        int row = i >> 5, c4 = i & 31;
        int gr = node0 + row;
        float4 v = (gr < n) ? ((const float4*)x)[gr * 32 + c4]
                            : make_float4(0.f, 0.f, 0.f, 0.f);
        *(__half2*)&As[row * LDA1 + c4 * 4] = __floats2half2_rn(v.x, v.y);
        *(__half2*)&As[row * LDA1 + c4 * 4 + 2] = __floats2half2_rn(v.z, v.w);
    }
    for (int i = tid; i < 4096; i += 512) {
        int hs = i >> 11;
        int f = i & 2047;
        int k = f >> 4, c4 = f & 15;
        float4 v = hs ? ((const float4*)Wr)[f] : ((const float4*)Wl)[f];
        int col = hs * 64 + c4 * 4;
        *(__half2*)&Bs[k * LDA1 + col] = __floats2half2_rn(v.x, v.y);
        *(__half2*)&Bs[k * LDA1 + col + 2] = __floats2half2_rn(v.z, v.w);
    }
    __syncthreads();

    int wid = tid >> 5;
    int wr = (wid & 7) * 16;
    int wc = (wid >> 3) * 64;
    wmma::fragment<wmma::accumulator, 16, 16, 16, float> acc[4];
#pragma unroll
    for (int j = 0; j < 4; j++) wmma::fill_fragment(acc[j], 0.f);

#pragma unroll
    for (int k = 0; k < 128; k += 16) {
        wmma::fragment<wmma::matrix_a, 16, 16, 16, __half, wmma::row_major> af;
        wmma::load_matrix_sync(af, &As[wr * LDA1 + k], LDA1);
#pragma unroll
        for (int j = 0; j < 4; j++) {
            wmma::fragment<wmma::matrix_b, 16, 16, 16, __half, wmma::row_major> bf;
            wmma::load_matrix_sync(bf, &Bs[k * LDA1 + wc + j * 16], LDA1);
            wmma::mma_sync(acc[j], af, bf, acc[j]);
        }
    }
    __syncthreads();
#pragma unroll
    for (int j = 0; j < 4; j++)
        wmma::store_matrix_sync(&Cs[wr * LDC1 + wc + j * 16], acc[j], LDC1,
                                wmma::mem_row_major);
    __syncthreads();

    for (int c = tid; c < 1024; c += 512) {         // y1h: 8 uint4/row
        int row = c >> 3, ci = c & 7;
        int m = node0 + row;
        if (m < n) {
            const float* cp = &Cs[row * LDC1 + ci * 8];
            __half2 h0 = __floats2half2_rn(cp[0], cp[1]);
            __half2 h1 = __floats2half2_rn(cp[2], cp[3]);
            __half2 h2 = __floats2half2_rn(cp[4], cp[5]);
            __half2 h3 = __floats2half2_rn(cp[6], cp[7]);
            uint4 u;
            u.x = *reinterpret_cast<uint32_t*>(&h0);
            u.y = *reinterpret_cast<uint32_t*>(&h1);
            u.z = *reinterpret_cast<uint32_t*>(&h2);
            u.w = *reinterpret_cast<uint32_t*>(&h3);
            ((uint4*)(g_y1h + (size_t)m * 64))[ci] = u;
        }
    }
    for (int c = tid; c < 1024; c += 512) {         // r1h: 8 uint4/row, +bias
        int row = c >> 3, ci = c & 7;
        int m = node0 + row;
        if (m < n) {
            const float* cp = &Cs[row * LDC1 + 64 + ci * 8];
            const float* bp = &bl[ci * 8];
            __half2 h0 = __floats2half2_rn(cp[0] + bp[0], cp[1] + bp[1]);
            __half2 h1 = __floats2half2_rn(cp[2] + bp[2], cp[3] + bp[3]);
            __half2 h2 = __floats2half2_rn(cp[4] + bp[4], cp[5] + bp[5]);
            __half2 h3 = __floats2half2_rn(cp[6] + bp[6], cp[7] + bp[7]);
            uint4 u;
            u.x = *reinterpret_cast<uint32_t*>(&h0);
            u.y = *reinterpret_cast<uint32_t*>(&h1);
            u.z = *reinterpret_cast<uint32_t*>(&h2);
            u.w = *reinterpret_cast<uint32_t*>(&h3);
            ((uint4*)(g_r1h + (size_t)m * 64))[ci] = u;
        }
    }
}

// ------- combine layer 1: hid = fp16(relu(gather_mean(y1) + r1)), MLP 4 --
__global__ void combine1_kernel(int n) {
    int node = (blockIdx.x * blockDim.x + threadIdx.x) >> 5;
    int lane = threadIdx.x & 31;
    if (node >= n) return;
    int s = g_rowstart[node];
    int dg = g_deg[node];
    int e = s + dg;
    float inv = 1.f / (float)max(dg, 1);
    const __half2* y1 = (const __half2*)g_y1h;
    float a0 = 0.f, a1 = 0.f, b0 = 0.f, b1 = 0.f;
    float c0 = 0.f, c1 = 0.f, d0 = 0.f, d1 = 0.f;
    for (int base = s; base < e; base += 32) {
        int cnt = min(32, e - base);
        int idx = (lane < cnt) ? g_ebuf[base + lane] : 0;
        int j = 0;
        for (; j + 4 <= cnt; j += 4) {
            int n0 = __shfl_sync(0xffffffffu, idx, j);
            int n1 = __shfl_sync(0xffffffffu, idx, j + 1);
            int n2 = __shfl_sync(0xffffffffu, idx, j + 2);
            int n3 = __shfl_sync(0xffffffffu, idx, j + 3);
            float2 v0 = __half22float2(y1[n0 * 32 + lane]);
            float2 v1 = __half22float2(y1[n1 * 32 + lane]);
            float2 v2 = __half22float2(y1[n2 * 32 + lane]);
            float2 v3 = __half22float2(y1[n3 * 32 + lane]);
            a0 += v0.x; a1 += v0.y;
            b0 += v1.x; b1 += v1.y;
            c0 += v2.x; c1 += v2.y;
            d0 += v3.x; d1 += v3.y;
        }
        for (; j < cnt; j++) {
            int n0 = __shfl_sync(0xffffffffu, idx, j);
            float2 v0 = __half22float2(y1[n0 * 32 + lane]);
            a0 += v0.x; a1 += v0.y;
        }
    }
    a0 += b0 + c0 + d0;
    a1 += b1 + c1 + d1;
    float2 r = __half22float2(*(const __half2*)&g_r1h[node * 64 + lane * 2]);
    float h0 = fmaxf(a0 * inv + r.x, 0.f);
    float h1 = fmaxf(a1 * inv + r.y, 0.f);
    *(__half2*)&g_hid[node * 64 + lane * 2] = __floats2half2_rn(h0, h1);
}

// ------- layer-2 HMMA, single pass: C[128,80] = hid_tile @ [Wl2|Wr2] ----
#define LDA2 72
#define LDB2 88
__global__ __launch_bounds__(256) void gemm2_kernel(
    const float* __restrict__ Wl, const float* __restrict__ Wr,
    const float* __restrict__ bl, int n) {
    extern __shared__ char smem[];
    __half* As = (__half*)smem;                       // [128][72]
    __half* Bs = (__half*)(smem + 128 * LDA2 * 2);    // [64][88]
    float*  Cs = (float*)smem;                        // [128][88] alias
    int tid = threadIdx.x;
    int node0 = blockIdx.x * 128;

    for (int i = tid; i < 128 * 8; i += 256) {
        int row = i >> 3, c8 = i & 7;
        int gr = node0 + row;
        uint4 v = (gr < n) ? ((const uint4*)g_hid)[gr * 8 + c8] : make_uint4(0, 0, 0, 0);
        *(uint4*)&As[row * LDA2 + c8 * 8] = v;
    }
    for (int i = tid; i < 1280; i += 256) {
        int hs = i >= 640;
        int f = hs ? i - 640 : i;
        int k = f / 10, c4 = f % 10;
        float4 v = hs ? ((const float4*)Wr)[f] : ((const float4*)Wl)[f];
        int col = hs * 40 + c4 * 4;
        *(__half2*)&Bs[k * LDB2 + col] = __floats2half2_rn(v.x, v.y);
        *(__half2*)&Bs[k * LDB2 + col + 2] = __floats2half2_rn(v.z, v.w);
    }
    for (int i = tid; i < 64 * 8; i += 256) {
        int k = i >> 3, c = i & 7;
        Bs[k * LDB2 + 80 + c] = __half(0.f);
    }
    __syncthreads();

    int wid = tid >> 5;
    int wr = wid * 16;
    wmma::fragment<wmma::accumulator, 16, 16, 16, float> acc[5];
#pragma unroll
    for (int j = 0; j < 5; j++) wmma::fill_fragment(acc[j], 0.f);
#pragma unroll
    for (int k = 0; k < 64; k += 16) {
        wmma::fragment<wmma::matrix_a, 16, 16, 16, __half, wmma::row_major> af;
        wmma::load_matrix_sync(af, &As[wr * LDA2 + k], LDA2);
#pragma unroll
        for (int j = 0; j < 5; j++) {
            wmma::fragment<wmma::matrix_b, 16, 16, 16, __half, wmma::row_major> bf;
            wmma::load_matrix_sync(bf, &Bs[k * LDB2 + j * 16], LDB2);
            wmma::mma_sync(acc[j], af, bf, acc[j]);
        }
    }
    __syncthreads();
#pragma unroll
    for (int j = 0; j < 5; j++)
        wmma::store_matrix_sync(&Cs[wr * LDB2 + j * 16], acc[j], LDB2,
                                wmma::mem_row_major);
    __syncthreads();

    for (int c = tid; c < 640; c += 256) {
        int row = c / 5, ci = c % 5;
        int m = node0 + row;
        if (m < n) {
            const float* cp = &Cs[row * LDB2 + ci * 8];
            __half2 h0 = __floats2half2_rn(cp[0], cp[1]);
            __half2 h1 = __floats2half2_rn(cp[2], cp[3]);
            __half2 h2 = __floats2half2_rn(cp[4], cp[5]);
            __half2 h3 = __floats2half2_rn(cp[6], cp[7]);
            uint4 u;
            u.x = *reinterpret_cast<uint32_t*>(&h0);
            u.y = *reinterpret_cast<uint32_t*>(&h1);
            u.z = *reinterpret_cast<uint32_t*>(&h2);
            u.w = *reinterpret_cast<uint32_t*>(&h3);
            ((uint4*)(g_y2h + (size_t)m * 40))[ci] = u;
        }
    }
    for (int c = tid; c < 640; c += 256) {
        int row = c / 5, ci = c % 5;
        int m = node0 + row;
        if (m < n) {
            const float* cp = &Cs[row * LDB2 + 40 + ci * 8];
            const float* bp = &bl[ci * 8];
            __half2 h0 = __floats2half2_rn(cp[0] + bp[0], cp[1] + bp[1]);
            __half2 h1 = __floats2half2_rn(cp[2] + bp[2], cp[3] + bp[3]);
            __half2 h2 = __floats2half2_rn(cp[4] + bp[4], cp[5] + bp[5]);
            __half2 h3 = __floats2half2_rn(cp[6] + bp[6], cp[7] + bp[7]);
            uint4 u;
            u.x = *reinterpret_cast<uint32_t*>(&h0);
            u.y = *reinterpret_cast<uint32_t*>(&h1);
            u.z = *reinterpret_cast<uint32_t*>(&h2);
            u.w = *reinterpret_cast<uint32_t*>(&h3);
            ((uint4*)(g_r2h + (size_t)m * 40))[ci] = u;
        }
    }
}

// ------- combine layer 2: out = log_softmax(gather_mean(y2) + r2) -------
__global__ void combine2_kernel(float* __restrict__ out, int n) {
    int node = (blockIdx.x * blockDim.x + threadIdx.x) >> 5;
    int lane = threadIdx.x & 31;
    if (node >= n) return;
    int s = g_rowstart[node];
    int dg = g_deg[node];
    int e = s + dg;
    float inv = 1.f / (float)max(dg, 1);
    const __half2* y2 = (const __half2*)g_y2h;
    bool act = lane < 20;
    float a0 = 0.f, a1 = 0.f, b0 = 0.f, b1 = 0.f;
    float c0 = 0.f, c1 = 0.f, d0 = 0.f, d1 = 0.f;
    for (int base = s; base < e; base += 32) {
        int cnt = min(32, e - base);
        int idx = (lane < cnt) ? g_ebuf[base + lane] : 0;
        int j = 0;
        for (; j + 4 <= cnt; j += 4) {
            int n0 = __shfl_sync(0xffffffffu, idx, j);
            int n1 = __shfl_sync(0xffffffffu, idx, j + 1);
            int n2 = __shfl_sync(0xffffffffu, idx, j + 2);
            int n3 = __shfl_sync(0xffffffffu, idx, j + 3);
            if (act) {
                float2 v0 = __half22float2(y2[n0 * 20 + lane]);
                float2 v1 = __half22float2(y2[n1 * 20 + lane]);
                float2 v2 = __half22float2(y2[n2 * 20 + lane]);
                float2 v3 = __half22float2(y2[n3 * 20 + lane]);
                a0 += v0.x; a1 += v0.y;
                b0 += v1.x; b1 += v1.y;
                c0 += v2.x; c1 += v2.y;
                d0 += v3.x; d1 += v3.y;
            }
        }
        for (; j < cnt; j++) {
            int n0 = __shfl_sync(0xffffffffu, idx, j);
            if (act) {
                float2 v0 = __half22float2(y2[n0 * 20 + lane]);
                a0 += v0.x; a1 += v0.y;
            }
        }
    }
    a0 += b0 + c0 + d0;
    a1 += b1 + c1 + d1;
    const float NEG_INF = __int_as_float(0xff800000);
    float v0 = NEG_INF, v1 = NEG_INF;
    if (act) {
        float2 r = __half22float2(*(const __half2*)&g_r2h[node * 40 + 2 * lane]);
        v0 = a0 * inv + r.x;
        v1 = a1 * inv + r.y;
    }
    float m = fmaxf(v0, v1);
#pragma unroll
    for (int o = 16; o > 0; o >>= 1) m = fmaxf(m, __shfl_xor_sync(0xffffffffu, m, o));
    float sum = act ? (expf(v0 - m) + expf(v1 - m)) : 0.f;
#pragma unroll
    for (int o = 16; o > 0; o >>= 1) sum += __shfl_xor_sync(0xffffffffu, sum, o);
    float lse = logf(sum);
    if (act) {
        out[node * 40 + 2 * lane] = v0 - m - lse;
        out[node * 40 + 2 * lane + 1] = v1 - m - lse;
    }
}

// ---------------- launch ----------------
extern "C" void kernel_launch(void* const* d_in, const int* in_sizes, int n_in,
                              void* d_out, int out_size) {
    const float* x   = (const float*)d_in[0];
    const int*   ei  = (const int*)d_in[1];   // int64 inputs delivered as int32
    const float* Wl1 = (const float*)d_in[2];
    const float* bl1 = (const float*)d_in[3];
    const float* Wr1 = (const float*)d_in[4];
    const float* Wl2 = (const float*)d_in[5];
    const float* bl2 = (const float*)d_in[6];
    const float* Wr2 = (const float*)d_in[7];
    float* out = (float*)d_out;

    int n = in_sizes[0] / 128;
    int e = in_sizes[1] / 2;
    const int* src = ei;
    const int* dst = ei + e;

    const int SMEM1 = 128 * LDA1 * 2 * 2;   // 69632 B
    const int SMEM2 = 128 * LDB2 * 4;       // 45056 B
    cudaFuncSetAttribute(gemm1_kernel, cudaFuncAttributeMaxDynamicSharedMemorySize, SMEM1);
    cudaFuncSetAttribute(gemm2_kernel, cudaFuncAttributeMaxDynamicSharedMemorySize, SMEM2);

    void* deg_ptr = nullptr;
    cudaGetSymbolAddress(&deg_ptr, g_deg);

    cudaStream_t s2;
    cudaStreamCreateWithFlags(&s2, cudaStreamNonBlocking);
    cudaEvent_t evFork, evJoin;
    cudaEventCreateWithFlags(&evFork, cudaEventDisableTiming);
    cudaEventCreateWithFlags(&evJoin, cudaEventDisableTiming);

    cudaEventRecord(evFork, 0);
    cudaStreamWaitEvent(s2, evFork, 0);

    // CSR chain (side stream): memset, count(+pos), assign, fill(no atomic)
    cudaMemsetAsync(deg_ptr, 0, (size_t)n * sizeof(int), s2);
    count_deg_kernel<<<(e + 255) / 256, 256, 0, s2>>>(dst, e);
    assign_kernel<<<(n + 255) / 256, 256, 0, s2>>>(n);
    fill_csr_kernel<<<(e + 255) / 256, 256, 0, s2>>>(src, dst, e);
    cudaEventRecord(evJoin, s2);

    int nblk = (n + 127) / 128;
    gemm1_kernel<<<nblk, 512, SMEM1>>>(x, Wl1, Wr1, bl1, n);

    cudaStreamWaitEvent(0, evJoin, 0);
    combine1_kernel<<<(n * 32 + 255) / 256, 256>>>(n);
    gemm2_kernel<<<nblk, 256, SMEM2>>>(Wl2, Wr2, bl2, n);
    combine2_kernel<<<(n * 32 + 255) / 256, 256>>>(out, n);
}

// round 16
// speedup vs baseline: 1.0898x; 1.0458x over previous
#include <cuda_runtime.h>
#include <cuda_fp16.h>
#include <mma.h>
#include <math.h>
#include <stdint.h>

using namespace nvcuda;

#define N_MAX 100000
#define E_MAX 1600000

// ---------------- device scratch (static, no allocation) ----------------
__device__ int    g_deg[N_MAX];
__device__ int    g_cursor[N_MAX];
__device__ int    g_rowstart[N_MAX];
__device__ int    g_total;
__device__ int    g_ebuf[E_MAX];
__device__ __align__(16) __half g_y1h[N_MAX * 64]; // fp16(x @ W_l1)
__device__ __align__(16) __half g_r1h[N_MAX * 64]; // fp16(x @ W_r1), bias in combine1
__device__ __align__(16) __half g_hid[N_MAX * 64]; // fp16(relu(mean + root + b))
__device__ __align__(16) __half g_y2h[N_MAX * 40]; // fp16(hid @ W_l2)
__device__ __align__(16) __half g_r2h[N_MAX * 40]; // fp16(hid @ W_r2 + b_l2)

// ---------------- CSR build (order-free segments, cursor atomic) --------
__global__ void count_deg_kernel(const int* __restrict__ dst, int e) {
    int i = blockIdx.x * blockDim.x + threadIdx.x;
    if (i == 0) g_total = 0;  // consumed only by assign_kernel (stream-ordered after)
    if (i < e) atomicAdd(&g_deg[dst[i]], 1);
}

__global__ void assign_kernel(int n) {
    __shared__ int wsum[32];
    __shared__ int blockbase;
    int t = threadIdx.x;
    int i = blockIdx.x * blockDim.x + t;
    int v = (i < n) ? g_deg[i] : 0;
    int x = v;
#pragma unroll
    for (int o = 1; o < 32; o <<= 1) {
        int u = __shfl_up_sync(0xffffffffu, x, o);
        if ((t & 31) >= o) x += u;
    }
    if ((t & 31) == 31) wsum[t >> 5] = x;
    __syncthreads();
    if (t < 32) {
        int w = (t < 8) ? wsum[t] : 0;
#pragma unroll
        for (int o = 1; o < 8; o <<= 1) {
            int u = __shfl_up_sync(0xffffffffu, w, o);
            if (t >= o) w += u;
        }
        if (t == 7) blockbase = atomicAdd(&g_total, w);
        wsum[t] = w;
    }
    __syncthreads();
    int base = blockbase + ((t >= 32) ? wsum[(t >> 5) - 1] : 0);
    if (i < n) {
        int rs = base + x - v;
        g_rowstart[i] = rs;
        g_cursor[i] = rs;
    }
}

__global__ void fill_csr_kernel(const int* __restrict__ src,
                                const int* __restrict__ dst, int e) {
    int i = blockIdx.x * blockDim.x + threadIdx.x;
    if (i < e) {
        int pos = atomicAdd(&g_cursor[dst[i]], 1);
        g_ebuf[pos] = src[i];
    }
}

// ------- layer-1 HMMA: C[128,128] = x_tile @ [Wl1|Wr1], half-C epilogue --
#define LDA1 136
__global__ __launch_bounds__(512) void gemm1_kernel(
    const float* __restrict__ x, const float* __restrict__ Wl,
    const float* __restrict__ Wr, int n) {
    extern __shared__ char smem[];
    __half* As = (__half*)smem;                        // [128][136] = 34816 B
    __half* Bs = (__half*)(smem + 128 * LDA1 * 2);     // [128][136] = 34816 B
    __half* Ch = (__half*)smem;                        // [128][136] half alias
    int tid = threadIdx.x;
    int node0 = blockIdx.x * 128;

    for (int i = tid; i < 128 * 32; i += 512) {
        int row = i >> 5, c4 = i & 31;
        int gr = node0 + row;
        float4 v = (gr < n) ? ((const float4*)x)[gr * 32 + c4]
                            : make_float4(0.f, 0.f, 0.f, 0.f);
        *(__half2*)&As[row * LDA1 + c4 * 4] = __floats2half2_rn(v.x, v.y);
        *(__half2*)&As[row * LDA1 + c4 * 4 + 2] = __floats2half2_rn(v.z, v.w);
    }
    for (int i = tid; i < 4096; i += 512) {
        int hs = i >> 11;
        int f = i & 2047;
        int k = f >> 4, c4 = f & 15;
        float4 v = hs ? ((const float4*)Wr)[f] : ((const float4*)Wl)[f];
        int col = hs * 64 + c4 * 4;
        *(__half2*)&Bs[k * LDA1 + col] = __floats2half2_rn(v.x, v.y);
        *(__half2*)&Bs[k * LDA1 + col + 2] = __floats2half2_rn(v.z, v.w);
    }
    __syncthreads();

    int wid = tid >> 5;
    int wr = (wid & 7) * 16;
    int wc = (wid >> 3) * 64;
    wmma::fragment<wmma::accumulator, 16, 16, 16, float> acc[4];
#pragma unroll
    for (int j = 0; j < 4; j++) wmma::fill_fragment(acc[j], 0.f);

#pragma unroll
    for (int k = 0; k < 128; k += 16) {
        wmma::fragment<wmma::matrix_a, 16, 16, 16, __half, wmma::row_major> af;
        wmma::load_matrix_sync(af, &As[wr * LDA1 + k], LDA1);
#pragma unroll
        for (int j = 0; j < 4; j++) {
            wmma::fragment<wmma::matrix_b, 16, 16, 16, __half, wmma::row_major> bf;
            wmma::load_matrix_sync(bf, &Bs[k * LDA1 + wc + j * 16], LDA1);
            wmma::mma_sync(acc[j], af, bf, acc[j]);
        }
    }
    __syncthreads();
    // convert accumulators to half in registers, store half C (halves L1 traffic)
    {
        wmma::fragment<wmma::accumulator, 16, 16, 16, __half> hacc;
#pragma unroll
        for (int j = 0; j < 4; j++) {
#pragma unroll
            for (int t = 0; t < hacc.num_elements; t++)
                hacc.x[t] = __float2half_rn(acc[j].x[t]);
            wmma::store_matrix_sync(&Ch[wr * LDA1 + wc + j * 16], hacc, LDA1,
                                    wmma::mem_row_major);
        }
    }
    __syncthreads();

    // pure-copy epilogue: y1h = cols 0..63, r1h = cols 64..127 (uint4 chunks)
    for (int c = tid; c < 1024; c += 512) {
        int row = c >> 3, ci = c & 7;
        int m = node0 + row;
        if (m < n)
            ((uint4*)(g_y1h + (size_t)m * 64))[ci] =
                *(const uint4*)&Ch[row * LDA1 + ci * 8];
    }
    for (int c = tid; c < 1024; c += 512) {
        int row = c >> 3, ci = c & 7;
        int m = node0 + row;
        if (m < n)
            ((uint4*)(g_r1h + (size_t)m * 64))[ci] =
                *(const uint4*)&Ch[row * LDA1 + 64 + ci * 8];
    }
}

// ------- combine layer 1: hid = fp16(relu(gather_mean(y1) + r1 + b)) ----
__global__ void combine1_kernel(const float* __restrict__ bl, int n) {
    int node = (blockIdx.x * blockDim.x + threadIdx.x) >> 5;
    int lane = threadIdx.x & 31;
    if (node >= n) return;
    int s = g_rowstart[node];
    int dg = g_deg[node];
    int e = s + dg;
    float inv = 1.f / (float)max(dg, 1);
    const __half2* y1 = (const __half2*)g_y1h;
    float a0 = 0.f, a1 = 0.f, b0 = 0.f, b1 = 0.f;
    float c0 = 0.f, c1 = 0.f, d0 = 0.f, d1 = 0.f;
    for (int base = s; base < e; base += 32) {
        int cnt = min(32, e - base);
        int idx = (lane < cnt) ? g_ebuf[base + lane] : 0;
        int j = 0;
        for (; j + 4 <= cnt; j += 4) {
            int n0 = __shfl_sync(0xffffffffu, idx, j);
            int n1 = __shfl_sync(0xffffffffu, idx, j + 1);
            int n2 = __shfl_sync(0xffffffffu, idx, j + 2);
            int n3 = __shfl_sync(0xffffffffu, idx, j + 3);
            float2 v0 = __half22float2(y1[n0 * 32 + lane]);
            float2 v1 = __half22float2(y1[n1 * 32 + lane]);
            float2 v2 = __half22float2(y1[n2 * 32 + lane]);
            float2 v3 = __half22float2(y1[n3 * 32 + lane]);
            a0 += v0.x; a1 += v0.y;
            b0 += v1.x; b1 += v1.y;
            c0 += v2.x; c1 += v2.y;
            d0 += v3.x; d1 += v3.y;
        }
        for (; j < cnt; j++) {
            int n0 = __shfl_sync(0xffffffffu, idx, j);
            float2 v0 = __half22float2(y1[n0 * 32 + lane]);
            a0 += v0.x; a1 += v0.y;
        }
    }
    a0 += b0 + c0 + d0;
    a1 += b1 + c1 + d1;
    float2 r = __half22float2(*(const __half2*)&g_r1h[node * 64 + lane * 2]);
    float h0 = fmaxf(a0 * inv + r.x + bl[lane * 2], 0.f);
    float h1 = fmaxf(a1 * inv + r.y + bl[lane * 2 + 1], 0.f);
    *(__half2*)&g_hid[node * 64 + lane * 2] = __floats2half2_rn(h0, h1);
}

// ------- layer-2 HMMA, single pass: C[128,80] = hid_tile @ [Wl2|Wr2] ----
#define LDA2 72
#define LDB2 88
__global__ __launch_bounds__(256) void gemm2_kernel(
    const float* __restrict__ Wl, const float* __restrict__ Wr,
    const float* __restrict__ bl, int n) {
    extern __shared__ char smem[];
    __half* As = (__half*)smem;                       // [128][72]
    __half* Bs = (__half*)(smem + 128 * LDA2 * 2);    // [64][88]
    float*  Cs = (float*)smem;                        // [128][88] alias
    int tid = threadIdx.x;
    int node0 = blockIdx.x * 128;

    for (int i = tid; i < 128 * 8; i += 256) {
        int row = i >> 3, c8 = i & 7;
        int gr = node0 + row;
        uint4 v = (gr < n) ? ((const uint4*)g_hid)[gr * 8 + c8] : make_uint4(0, 0, 0, 0);
        *(uint4*)&As[row * LDA2 + c8 * 8] = v;
    }
    for (int i = tid; i < 1280; i += 256) {
        int hs = i >= 640;
        int f = hs ? i - 640 : i;
        int k = f / 10, c4 = f % 10;
        float4 v = hs ? ((const float4*)Wr)[f] : ((const float4*)Wl)[f];
        int col = hs * 40 + c4 * 4;
        *(__half2*)&Bs[k * LDB2 + col] = __floats2half2_rn(v.x, v.y);
        *(__half2*)&Bs[k * LDB2 + col + 2] = __floats2half2_rn(v.z, v.w);
    }
    for (int i = tid; i < 64 * 8; i += 256) {
        int k = i >> 3, c = i & 7;
        Bs[k * LDB2 + 80 + c] = __half(0.f);
    }
    __syncthreads();

    int wid = tid >> 5;
    int wr = wid * 16;
    wmma::fragment<wmma::accumulator, 16, 16, 16, float> acc[5];
#pragma unroll
    for (int j = 0; j < 5; j++) wmma::fill_fragment(acc[j], 0.f);
#pragma unroll
    for (int k = 0; k < 64; k += 16) {
        wmma::fragment<wmma::matrix_a, 16, 16, 16, __half, wmma::row_major> af;
        wmma::load_matrix_sync(af, &As[wr * LDA2 + k], LDA2);
#pragma unroll
        for (int j = 0; j < 5; j++) {
            wmma::fragment<wmma::matrix_b, 16, 16, 16, __half, wmma::row_major> bf;
            wmma::load_matrix_sync(bf, &Bs[k * LDB2 + j * 16], LDB2);
            wmma::mma_sync(acc[j], af, bf, acc[j]);
        }
    }
    __syncthreads();
#pragma unroll
    for (int j = 0; j < 5; j++)
        wmma::store_matrix_sync(&Cs[wr * LDB2 + j * 16], acc[j], LDB2,
                                wmma::mem_row_major);
    __syncthreads();

    for (int c = tid; c < 640; c += 256) {
        int row = c / 5, ci = c % 5;
        int m = node0 + row;
        if (m < n) {
            const float* cp = &Cs[row * LDB2 + ci * 8];
            __half2 h0 = __floats2half2_rn(cp[0], cp[1]);
            __half2 h1 = __floats2half2_rn(cp[2], cp[3]);
            __half2 h2 = __floats2half2_rn(cp[4], cp[5]);
            __half2 h3 = __floats2half2_rn(cp[6], cp[7]);
            uint4 u;
            u.x = *reinterpret_cast<uint32_t*>(&h0);
            u.y = *reinterpret_cast<uint32_t*>(&h1);
            u.z = *reinterpret_cast<uint32_t*>(&h2);
            u.w = *reinterpret_cast<uint32_t*>(&h3);
            ((uint4*)(g_y2h + (size_t)m * 40))[ci] = u;
        }
    }
    for (int c = tid; c < 640; c += 256) {
        int row = c / 5, ci = c % 5;
        int m = node0 + row;
        if (m < n) {
            const float* cp = &Cs[row * LDB2 + 40 + ci * 8];
            const float* bp = &bl[ci * 8];
            __half2 h0 = __floats2half2_rn(cp[0] + bp[0], cp[1] + bp[1]);
            __half2 h1 = __floats2half2_rn(cp[2] + bp[2], cp[3] + bp[3]);
            __half2 h2 = __floats2half2_rn(cp[4] + bp[4], cp[5] + bp[5]);
            __half2 h3 = __floats2half2_rn(cp[6] + bp[6], cp[7] + bp[7]);
            uint4 u;
            u.x = *reinterpret_cast<uint32_t*>(&h0);
            u.y = *reinterpret_cast<uint32_t*>(&h1);
            u.z = *reinterpret_cast<uint32_t*>(&h2);
            u.w = *reinterpret_cast<uint32_t*>(&h3);
            ((uint4*)(g_r2h + (size_t)m * 40))[ci] = u;
        }
    }
}

// ------- combine layer 2: out = log_softmax(gather_mean(y2) + r2) -------
__global__ void combine2_kernel(float* __restrict__ out, int n) {
    int node = (blockIdx.x * blockDim.x + threadIdx.x) >> 5;
    int lane = threadIdx.x & 31;
    if (node >= n) return;
    int s = g_rowstart[node];
    int dg = g_deg[node];
    int e = s + dg;
    float inv = 1.f / (float)max(dg, 1);
    const __half2* y2 = (const __half2*)g_y2h;
    bool act = lane < 20;
    float a0 = 0.f, a1 = 0.f, b0 = 0.f, b1 = 0.f;
    float c0 = 0.f, c1 = 0.f, d0 = 0.f, d1 = 0.f;
    for (int base = s; base < e; base += 32) {
        int cnt = min(32, e - base);
        int idx = (lane < cnt) ? g_ebuf[base + lane] : 0;
        int j = 0;
        for (; j + 4 <= cnt; j += 4) {
            int n0 = __shfl_sync(0xffffffffu, idx, j);
            int n1 = __shfl_sync(0xffffffffu, idx, j + 1);
            int n2 = __shfl_sync(0xffffffffu, idx, j + 2);
            int n3 = __shfl_sync(0xffffffffu, idx, j + 3);
            if (act) {
                float2 v0 = __half22float2(y2[n0 * 20 + lane]);
                float2 v1 = __half22float2(y2[n1 * 20 + lane]);
                float2 v2 = __half22float2(y2[n2 * 20 + lane]);
                float2 v3 = __half22float2(y2[n3 * 20 + lane]);
                a0 += v0.x; a1 += v0.y;
                b0 += v1.x; b1 += v1.y;
                c0 += v2.x; c1 += v2.y;
                d0 += v3.x; d1 += v3.y;
            }
        }
        for (; j < cnt; j++) {
            int n0 = __shfl_sync(0xffffffffu, idx, j);
            if (act) {
                float2 v0 = __half22float2(y2[n0 * 20 + lane]);
                a0 += v0.x; a1 += v0.y;
            }
        }
    }
    a0 += b0 + c0 + d0;
    a1 += b1 + c1 + d1;
    const float NEG_INF = __int_as_float(0xff800000);
    float v0 = NEG_INF, v1 = NEG_INF;
    if (act) {
        float2 r = __half22float2(*(const __half2*)&g_r2h[node * 40 + 2 * lane]);
        v0 = a0 * inv + r.x;
        v1 = a1 * inv + r.y;
    }
    float m = fmaxf(v0, v1);
#pragma unroll
    for (int o = 16; o > 0; o >>= 1) m = fmaxf(m, __shfl_xor_sync(0xffffffffu, m, o));
    float sum = act ? (expf(v0 - m) + expf(v1 - m)) : 0.f;
#pragma unroll
    for (int o = 16; o > 0; o >>= 1) sum += __shfl_xor_sync(0xffffffffu, sum, o);
    float lse = logf(sum);
    if (act) {
        out[node * 40 + 2 * lane] = v0 - m - lse;
        out[node * 40 + 2 * lane + 1] = v1 - m - lse;
    }
}

// ---------------- launch ----------------
extern "C" void kernel_launch(void* const* d_in, const int* in_sizes, int n_in,
                              void* d_out, int out_size) {
    const float* x   = (const float*)d_in[0];
    const int*   ei  = (const int*)d_in[1];   // int64 inputs delivered as int32
    const float* Wl1 = (const float*)d_in[2];
    const float* bl1 = (const float*)d_in[3];
    const float* Wr1 = (const float*)d_in[4];
    const float* Wl2 = (const float*)d_in[5];
    const float* bl2 = (const float*)d_in[6];
    const float* Wr2 = (const float*)d_in[7];
    float* out = (float*)d_out;

    int n = in_sizes[0] / 128;
    int e = in_sizes[1] / 2;
    const int* src = ei;
    const int* dst = ei + e;

    const int SMEM1 = 128 * LDA1 * 2 * 2;   // 69632 B
    const int SMEM2 = 128 * LDB2 * 4;       // 45056 B
    cudaFuncSetAttribute(gemm1_kernel, cudaFuncAttributeMaxDynamicSharedMemorySize, SMEM1);
    cudaFuncSetAttribute(gemm2_kernel, cudaFuncAttributeMaxDynamicSharedMemorySize, SMEM2);

    void* deg_ptr = nullptr;
    cudaGetSymbolAddress(&deg_ptr, g_deg);

    cudaStream_t s2;
    cudaStreamCreateWithFlags(&s2, cudaStreamNonBlocking);
    cudaEvent_t evFork, evJoin;
    cudaEventCreateWithFlags(&evFork, cudaEventDisableTiming);
    cudaEventCreateWithFlags(&evJoin, cudaEventDisableTiming);

    cudaEventRecord(evFork, 0);
    cudaStreamWaitEvent(s2, evFork, 0);

    // CSR chain (side stream): memset, count, assign(cursor:=rowstart), fill
    cudaMemsetAsync(deg_ptr, 0, (size_t)n * sizeof(int), s2);
    count_deg_kernel<<<(e + 255) / 256, 256, 0, s2>>>(dst, e);
    assign_kernel<<<(n + 255) / 256, 256, 0, s2>>>(n);
    fill_csr_kernel<<<(e + 255) / 256, 256, 0, s2>>>(src, dst, e);
    cudaEventRecord(evJoin, s2);

    int nblk = (n + 127) / 128;
    gemm1_kernel<<<nblk, 512, SMEM1>>>(x, Wl1, Wr1, n);

    cudaStreamWaitEvent(0, evJoin, 0);
    combine1_kernel<<<(n * 32 + 255) / 256, 256>>>(bl1, n);
    gemm2_kernel<<<nblk, 256, SMEM2>>>(Wl2, Wr2, bl2, n);
    combine2_kernel<<<(n * 32 + 255) / 256, 256>>>(out, n);
}

// round 17
// speedup vs baseline: 1.1057x; 1.0146x over previous
#include <cuda_runtime.h>
#include <cuda_fp16.h>
#include <mma.h>
#include <math.h>
#include <stdint.h>

using namespace nvcuda;

#define N_MAX 100000
#define E_MAX 1600000

// ---------------- device scratch (static, no allocation) ----------------
__device__ int    g_deg[N_MAX];
__device__ int    g_cursor[N_MAX];
__device__ int    g_rowstart[N_MAX];
__device__ int    g_total;
__device__ int    g_ebuf[E_MAX];
__device__ __align__(16) __half g_y1h[N_MAX * 64]; // fp16(x @ W_l1)
__device__ __align__(16) __half g_r1h[N_MAX * 64]; // fp16(x @ W_r1), bias in combine1
__device__ __align__(16) __half g_hid[N_MAX * 64]; // fp16(relu(mean + root + b))
__device__ __align__(16) __half g_y2h[N_MAX * 40]; // fp16(hid @ W_l2)
__device__ __align__(16) __half g_r2h[N_MAX * 40]; // fp16(hid @ W_r2), bias in combine2

// ---------------- CSR build (order-free segments, cursor atomic) --------
__global__ void count_deg_kernel(const int* __restrict__ dst, int e) {
    int i = blockIdx.x * blockDim.x + threadIdx.x;
    if (i == 0) g_total = 0;  // consumed only by assign_kernel (stream-ordered after)
    if (i < e) atomicAdd(&g_deg[dst[i]], 1);
}

__global__ void assign_kernel(int n) {
    __shared__ int wsum[32];
    __shared__ int blockbase;
    int t = threadIdx.x;
    int i = blockIdx.x * blockDim.x + t;
    int v = (i < n) ? g_deg[i] : 0;
    int x = v;
#pragma unroll
    for (int o = 1; o < 32; o <<= 1) {
        int u = __shfl_up_sync(0xffffffffu, x, o);
        if ((t & 31) >= o) x += u;
    }
    if ((t & 31) == 31) wsum[t >> 5] = x;
    __syncthreads();
    if (t < 32) {
        int w = (t < 8) ? wsum[t] : 0;
#pragma unroll
        for (int o = 1; o < 8; o <<= 1) {
            int u = __shfl_up_sync(0xffffffffu, w, o);
            if (t >= o) w += u;
        }
        if (t == 7) blockbase = atomicAdd(&g_total, w);
        wsum[t] = w;
    }
    __syncthreads();
    int base = blockbase + ((t >= 32) ? wsum[(t >> 5) - 1] : 0);
    if (i < n) {
        int rs = base + x - v;
        g_rowstart[i] = rs;
        g_cursor[i] = rs;
    }
}

__global__ void fill_csr_kernel(const int* __restrict__ src,
                                const int* __restrict__ dst, int e) {
    int i = blockIdx.x * blockDim.x + threadIdx.x;
    if (i < e) {
        int pos = atomicAdd(&g_cursor[dst[i]], 1);
        g_ebuf[pos] = src[i];
    }
}

// ------- layer-1 HMMA: C[128,128] = x_tile @ [Wl1|Wr1], half-C epilogue --
#define LDA1 136
__global__ __launch_bounds__(512) void gemm1_kernel(
    const float* __restrict__ x, const float* __restrict__ Wl,
    const float* __restrict__ Wr, int n) {
    extern __shared__ char smem[];
    __half* As = (__half*)smem;                        // [128][136] = 34816 B
    __half* Bs = (__half*)(smem + 128 * LDA1 * 2);     // [128][136] = 34816 B
    __half* Ch = (__half*)smem;                        // [128][136] half alias
    int tid = threadIdx.x;
    int node0 = blockIdx.x * 128;

    for (int i = tid; i < 128 * 32; i += 512) {
        int row = i >> 5, c4 = i & 31;
        int gr = node0 + row;
        float4 v = (gr < n) ? ((const float4*)x)[gr * 32 + c4]
                            : make_float4(0.f, 0.f, 0.f, 0.f);
        *(__half2*)&As[row * LDA1 + c4 * 4] = __floats2half2_rn(v.x, v.y);
        *(__half2*)&As[row * LDA1 + c4 * 4 + 2] = __floats2half2_rn(v.z, v.w);
    }
    for (int i = tid; i < 4096; i += 512) {
        int hs = i >> 11;
        int f = i & 2047;
        int k = f >> 4, c4 = f & 15;
        float4 v = hs ? ((const float4*)Wr)[f] : ((const float4*)Wl)[f];
        int col = hs * 64 + c4 * 4;
        *(__half2*)&Bs[k * LDA1 + col] = __floats2half2_rn(v.x, v.y);
        *(__half2*)&Bs[k * LDA1 + col + 2] = __floats2half2_rn(v.z, v.w);
    }
    __syncthreads();

    int wid = tid >> 5;
    int wr = (wid & 7) * 16;
    int wc = (wid >> 3) * 64;
    wmma::fragment<wmma::accumulator, 16, 16, 16, float> acc[4];
#pragma unroll
    for (int j = 0; j < 4; j++) wmma::fill_fragment(acc[j], 0.f);

#pragma unroll
    for (int k = 0; k < 128; k += 16) {
        wmma::fragment<wmma::matrix_a, 16, 16, 16, __half, wmma::row_major> af;
        wmma::load_matrix_sync(af, &As[wr * LDA1 + k], LDA1);
#pragma unroll
        for (int j = 0; j < 4; j++) {
            wmma::fragment<wmma::matrix_b, 16, 16, 16, __half, wmma::row_major> bf;
            wmma::load_matrix_sync(bf, &Bs[k * LDA1 + wc + j * 16], LDA1);
            wmma::mma_sync(acc[j], af, bf, acc[j]);
        }
    }
    __syncthreads();
    {
        wmma::fragment<wmma::accumulator, 16, 16, 16, __half> hacc;
#pragma unroll
        for (int j = 0; j < 4; j++) {
#pragma unroll
            for (int t = 0; t < hacc.num_elements; t++)
                hacc.x[t] = __float2half_rn(acc[j].x[t]);
            wmma::store_matrix_sync(&Ch[wr * LDA1 + wc + j * 16], hacc, LDA1,
                                    wmma::mem_row_major);
        }
    }
    __syncthreads();

    for (int c = tid; c < 1024; c += 512) {
        int row = c >> 3, ci = c & 7;
        int m = node0 + row;
        if (m < n)
            ((uint4*)(g_y1h + (size_t)m * 64))[ci] =
                *(const uint4*)&Ch[row * LDA1 + ci * 8];
    }
    for (int c = tid; c < 1024; c += 512) {
        int row = c >> 3, ci = c & 7;
        int m = node0 + row;
        if (m < n)
            ((uint4*)(g_r1h + (size_t)m * 64))[ci] =
                *(const uint4*)&Ch[row * LDA1 + 64 + ci * 8];
    }
}

// ------- combine layer 1: hid = fp16(relu(gather_mean(y1) + r1 + b)) ----
__global__ void combine1_kernel(const float* __restrict__ bl, int n) {
    int node = (blockIdx.x * blockDim.x + threadIdx.x) >> 5;
    int lane = threadIdx.x & 31;
    if (node >= n) return;
    int s = g_rowstart[node];
    int dg = g_deg[node];
    int e = s + dg;
    float inv = 1.f / (float)max(dg, 1);
    const __half2* y1 = (const __half2*)g_y1h;
    float a0 = 0.f, a1 = 0.f, b0 = 0.f, b1 = 0.f;
    float c0 = 0.f, c1 = 0.f, d0 = 0.f, d1 = 0.f;
    for (int base = s; base < e; base += 32) {
        int cnt = min(32, e - base);
        int idx = (lane < cnt) ? g_ebuf[base + lane] : 0;
        int j = 0;
        for (; j + 4 <= cnt; j += 4) {
            int n0 = __shfl_sync(0xffffffffu, idx, j);
            int n1 = __shfl_sync(0xffffffffu, idx, j + 1);
            int n2 = __shfl_sync(0xffffffffu, idx, j + 2);
            int n3 = __shfl_sync(0xffffffffu, idx, j + 3);
            float2 v0 = __half22float2(y1[n0 * 32 + lane]);
            float2 v1 = __half22float2(y1[n1 * 32 + lane]);
            float2 v2 = __half22float2(y1[n2 * 32 + lane]);
            float2 v3 = __half22float2(y1[n3 * 32 + lane]);
            a0 += v0.x; a1 += v0.y;
            b0 += v1.x; b1 += v1.y;
            c0 += v2.x; c1 += v2.y;
            d0 += v3.x; d1 += v3.y;
        }
        for (; j < cnt; j++) {
            int n0 = __shfl_sync(0xffffffffu, idx, j);
            float2 v0 = __half22float2(y1[n0 * 32 + lane]);
            a0 += v0.x; a1 += v0.y;
        }
    }
    a0 += b0 + c0 + d0;
    a1 += b1 + c1 + d1;
    float2 r = __half22float2(*(const __half2*)&g_r1h[node * 64 + lane * 2]);
    float h0 = fmaxf(a0 * inv + r.x + bl[lane * 2], 0.f);
    float h1 = fmaxf(a1 * inv + r.y + bl[lane * 2 + 1], 0.f);
    *(__half2*)&g_hid[node * 64 + lane * 2] = __floats2half2_rn(h0, h1);
}

// ------- layer-2 HMMA: C[128,80] = hid_tile @ [Wl2|Wr2], half-C epilogue -
#define LDA2 72
#define LDB2 88
__global__ __launch_bounds__(256) void gemm2_kernel(
    const float* __restrict__ Wl, const float* __restrict__ Wr, int n) {
    extern __shared__ char smem[];
    __half* As = (__half*)smem;                       // [128][72]  = 18432 B
    __half* Bs = (__half*)(smem + 128 * LDA2 * 2);    // [64][88]   = 11264 B
    __half* Ch = (__half*)smem;                       // [128][88] half alias = 22528 B
    int tid = threadIdx.x;
    int node0 = blockIdx.x * 128;

    for (int i = tid; i < 128 * 8; i += 256) {
        int row = i >> 3, c8 = i & 7;
        int gr = node0 + row;
        uint4 v = (gr < n) ? ((const uint4*)g_hid)[gr * 8 + c8] : make_uint4(0, 0, 0, 0);
        *(uint4*)&As[row * LDA2 + c8 * 8] = v;
    }
    for (int i = tid; i < 1280; i += 256) {
        int hs = i >= 640;
        int f = hs ? i - 640 : i;
        int k = f / 10, c4 = f % 10;
        float4 v = hs ? ((const float4*)Wr)[f] : ((const float4*)Wl)[f];
        int col = hs * 40 + c4 * 4;
        *(__half2*)&Bs[k * LDB2 + col] = __floats2half2_rn(v.x, v.y);
        *(__half2*)&Bs[k * LDB2 + col + 2] = __floats2half2_rn(v.z, v.w);
    }
    for (int i = tid; i < 64 * 8; i += 256) {
        int k = i >> 3, c = i & 7;
        Bs[k * LDB2 + 80 + c] = __half(0.f);
    }
    __syncthreads();

    int wid = tid >> 5;
    int wr = wid * 16;
    wmma::fragment<wmma::accumulator, 16, 16, 16, float> acc[5];
#pragma unroll
    for (int j = 0; j < 5; j++) wmma::fill_fragment(acc[j], 0.f);
#pragma unroll
    for (int k = 0; k < 64; k += 16) {
        wmma::fragment<wmma::matrix_a, 16, 16, 16, __half, wmma::row_major> af;
        wmma::load_matrix_sync(af, &As[wr * LDA2 + k], LDA2);
#pragma unroll
        for (int j = 0; j < 5; j++) {
            wmma::fragment<wmma::matrix_b, 16, 16, 16, __half, wmma::row_major> bf;
            wmma::load_matrix_sync(bf, &Bs[k * LDB2 + j * 16], LDB2);
            wmma::mma_sync(acc[j], af, bf, acc[j]);
        }
    }
    __syncthreads();
    {
        wmma::fragment<wmma::accumulator, 16, 16, 16, __half> hacc;
#pragma unroll
        for (int j = 0; j < 5; j++) {
#pragma unroll
            for (int t = 0; t < hacc.num_elements; t++)
                hacc.x[t] = __float2half_rn(acc[j].x[t]);
            wmma::store_matrix_sync(&Ch[wr * LDB2 + j * 16], hacc, LDB2,
                                    wmma::mem_row_major);
        }
    }
    __syncthreads();

    // pure-copy epilogue: y2h = cols 0..39, r2h = cols 40..79 (5 uint4/row each)
    for (int c = tid; c < 640; c += 256) {
        int row = c / 5, ci = c % 5;
        int m = node0 + row;
        if (m < n)
            ((uint4*)(g_y2h + (size_t)m * 40))[ci] =
                *(const uint4*)&Ch[row * LDB2 + ci * 8];
    }
    for (int c = tid; c < 640; c += 256) {
        int row = c / 5, ci = c % 5;
        int m = node0 + row;
        if (m < n)
            ((uint4*)(g_r2h + (size_t)m * 40))[ci] =
                *(const uint4*)&Ch[row * LDB2 + 40 + ci * 8];
    }
}

// ------- combine layer 2: out = log_softmax(gather_mean(y2) + r2 + b) ---
__global__ void combine2_kernel(const float* __restrict__ bl,
                                float* __restrict__ out, int n) {
    int node = (blockIdx.x * blockDim.x + threadIdx.x) >> 5;
    int lane = threadIdx.x & 31;
    if (node >= n) return;
    int s = g_rowstart[node];
    int dg = g_deg[node];
    int e = s + dg;
    float inv = 1.f / (float)max(dg, 1);
    const __half2* y2 = (const __half2*)g_y2h;
    bool act = lane < 20;
    float a0 = 0.f, a1 = 0.f, b0 = 0.f, b1 = 0.f;
    float c0 = 0.f, c1 = 0.f, d0 = 0.f, d1 = 0.f;
    for (int base = s; base < e; base += 32) {
        int cnt = min(32, e - base);
        int idx = (lane < cnt) ? g_ebuf[base + lane] : 0;
        int j = 0;
        for (; j + 4 <= cnt; j += 4) {
            int n0 = __shfl_sync(0xffffffffu, idx, j);
            int n1 = __shfl_sync(0xffffffffu, idx, j + 1);
            int n2 = __shfl_sync(0xffffffffu, idx, j + 2);
            int n3 = __shfl_sync(0xffffffffu, idx, j + 3);
            if (act) {
                float2 v0 = __half22float2(y2[n0 * 20 + lane]);
                float2 v1 = __half22float2(y2[n1 * 20 + lane]);
                float2 v2 = __half22float2(y2[n2 * 20 + lane]);
                float2 v3 = __half22float2(y2[n3 * 20 + lane]);
                a0 += v0.x; a1 += v0.y;
                b0 += v1.x; b1 += v1.y;
                c0 += v2.x; c1 += v2.y;
                d0 += v3.x; d1 += v3.y;
            }
        }
        for (; j < cnt; j++) {
            int n0 = __shfl_sync(0xffffffffu, idx, j);
            if (act) {
                float2 v0 = __half22float2(y2[n0 * 20 + lane]);
                a0 += v0.x; a1 += v0.y;
            }
        }
    }
    a0 += b0 + c0 + d0;
    a1 += b1 + c1 + d1;
    const float NEG_INF = __int_as_float(0xff800000);
    float v0 = NEG_INF, v1 = NEG_INF;
    if (act) {
        float2 r = __half22float2(*(const __half2*)&g_r2h[node * 40 + 2 * lane]);
        v0 = a0 * inv + r.x + bl[2 * lane];
        v1 = a1 * inv + r.y + bl[2 * lane + 1];
    }
    float m = fmaxf(v0, v1);
#pragma unroll
    for (int o = 16; o > 0; o >>= 1) m = fmaxf(m, __shfl_xor_sync(0xffffffffu, m, o));
    float sum = act ? (expf(v0 - m) + expf(v1 - m)) : 0.f;
#pragma unroll
    for (int o = 16; o > 0; o >>= 1) sum += __shfl_xor_sync(0xffffffffu, sum, o);
    float lse = logf(sum);
    if (act) {
        out[node * 40 + 2 * lane] = v0 - m - lse;
        out[node * 40 + 2 * lane + 1] = v1 - m - lse;
    }
}

// ---------------- launch ----------------
extern "C" void kernel_launch(void* const* d_in, const int* in_sizes, int n_in,
                              void* d_out, int out_size) {
    const float* x   = (const float*)d_in[0];
    const int*   ei  = (const int*)d_in[1];   // int64 inputs delivered as int32
    const float* Wl1 = (const float*)d_in[2];
    const float* bl1 = (const float*)d_in[3];
    const float* Wr1 = (const float*)d_in[4];
    const float* Wl2 = (const float*)d_in[5];
    const float* bl2 = (const float*)d_in[6];
    const float* Wr2 = (const float*)d_in[7];
    float* out = (float*)d_out;

    int n = in_sizes[0] / 128;
    int e = in_sizes[1] / 2;
    const int* src = ei;
    const int* dst = ei + e;

    const int SMEM1 = 128 * LDA1 * 2 * 2;            // 69632 B
    const int SMEM2 = 128 * LDA2 * 2 + 64 * LDB2 * 2; // 29696 B (A+B; half-C alias fits)
    cudaFuncSetAttribute(gemm1_kernel, cudaFuncAttributeMaxDynamicSharedMemorySize, SMEM1);
    cudaFuncSetAttribute(gemm2_kernel, cudaFuncAttributeMaxDynamicSharedMemorySize, SMEM2);

    void* deg_ptr = nullptr;
    cudaGetSymbolAddress(&deg_ptr, g_deg);

    cudaStream_t s2;
    cudaStreamCreateWithFlags(&s2, cudaStreamNonBlocking);
    cudaEvent_t evFork, evJoin;
    cudaEventCreateWithFlags(&evFork, cudaEventDisableTiming);
    cudaEventCreateWithFlags(&evJoin, cudaEventDisableTiming);

    cudaEventRecord(evFork, 0);
    cudaStreamWaitEvent(s2, evFork, 0);

    // CSR chain (side stream): memset, count, assign(cursor:=rowstart), fill
    cudaMemsetAsync(deg_ptr, 0, (size_t)n * sizeof(int), s2);
    count_deg_kernel<<<(e + 255) / 256, 256, 0, s2>>>(dst, e);
    assign_kernel<<<(n + 255) / 256, 256, 0, s2>>>(n);
    fill_csr_kernel<<<(e + 255) / 256, 256, 0, s2>>>(src, dst, e);
    cudaEventRecord(evJoin, s2);

    int nblk = (n + 127) / 128;
    gemm1_kernel<<<nblk, 512, SMEM1>>>(x, Wl1, Wr1, n);

    cudaStreamWaitEvent(0, evJoin, 0);
    combine1_kernel<<<(n * 32 + 255) / 256, 256>>>(bl1, n);
    gemm2_kernel<<<nblk, 256, SMEM2>>>(Wl2, Wr2, n);
    combine2_kernel<<<(n * 32 + 255) / 256, 256>>>(bl2, out, n);
}